// round 13
// baseline (speedup 1.0000x reference)
#include <cuda_runtime.h>
#include <cstdint>

#define HF 64
#define WF 64
#define CC 256
#define NB 4
#define KK 2048

// NHWC feature map: [N][64][64][C] = 16 MB
__device__ float g_nhwc[NB * HF * WF * CC];
// Row-pair max: H1[n][h2][w][c] = max over rows {2h2, 2h2+1}   (8 MB)
__device__ float g_h1[NB * (HF / 2) * WF * CC];
// Per-(roi,bin) window bounds, packed: (hs, he, ws, we)         (1.6 MB)
__device__ int4 g_bounds[KK * 49];

__device__ __forceinline__ float4 fmax4(float4 a, float4 b) {
    a.x = fmaxf(a.x, b.x);
    a.y = fmaxf(a.y, b.y);
    a.z = fmaxf(a.z, b.z);
    a.w = fmaxf(a.w, b.w);
    return a;
}

// ---------------------------------------------------------------------------
// Kernel 1 (fused prologue): NCHW -> NHWC transpose + H1 row-pair max,
// PLUS the per-(roi,bin) bounds table (first 392 of 1024 blocks compute one
// 256-entry chunk each — hides under the transpose's memory latency).
// grid = (HF/2, CC/32, NB) = (32, 8, 4); 256 threads (32 x 8).
// ---------------------------------------------------------------------------
__global__ void transpose_build(const float* __restrict__ in,
                                const float* __restrict__ rois) {
    __shared__ float tile[32][129];   // stride 129: odd -> conflict-free columns
    const int n  = blockIdx.z;
    const int c0 = blockIdx.y * 32;
    const int h2 = blockIdx.x;
    const int s0 = h2 * 128;          // s = h*WF + w; two rows = 128 contiguous s

    const int tid = threadIdx.y * 32 + threadIdx.x;
    const int sx  = threadIdx.x;      // 0..31
    const int cy  = threadIdx.y;      // 0..7

    // ---- bounds-table side job (blocks 0..391 cover 392*256 = 100352) ----
    const int bid = ((blockIdx.z * gridDim.y) + blockIdx.y) * gridDim.x + blockIdx.x;
    if (bid < (KK * 49 + 255) / 256) {
        const int i = bid * 256 + tid;
        if (i < KK * 49) {
            const int k  = i / 49;
            const int bi = i - k * 49;
            const int ph = bi / 7;
            const int pw = bi - ph * 7;

            const float* r = rois + (size_t)k * 5;
            const int rsw = __float2int_rn(r[1] * 0.0625f);  // round-half-even
            const int rsh = __float2int_rn(r[2] * 0.0625f);
            const int rew = __float2int_rn(r[3] * 0.0625f);
            const int reh = __float2int_rn(r[4] * 0.0625f);
            // Reciprocal-multiply division matches the reference's XLA
            // lowering (verified R2: rel_err == 0). Do not change.
            const float RCP7  = 1.0f / 7.0f;
            const float bin_h = (float)max(reh - rsh + 1, 1) * RCP7;
            const float bin_w = (float)max(rew - rsw + 1, 1) * RCP7;

            int hs = min(max((int)floorf((float)ph * bin_h) + rsh, 0), HF);
            int he = min(max((int)ceilf((float)(ph + 1) * bin_h) + rsh, 0), HF);
            int ws = min(max((int)floorf((float)pw * bin_w) + rsw, 0), WF);
            int we = min(max((int)ceilf((float)(pw + 1) * bin_w) + rsw, 0), WF);

            g_bounds[i] = make_int4(hs, he, ws, we);
        }
    }

    // ---- transpose + H1 ----
    const float* inp = in + (size_t)n * CC * (HF * WF);
#pragma unroll
    for (int j = 0; j < 32; j += 8) {
#pragma unroll
        for (int i = 0; i < 128; i += 32) {
            tile[cy + j][i + sx] =
                inp[(size_t)(c0 + cy + j) * (HF * WF) + s0 + i + sx];
        }
    }
    __syncthreads();

    float* outp = g_nhwc + ((size_t)n * (HF * WF) + s0) * CC + c0;
#pragma unroll
    for (int i = 0; i < 16; ++i) {
        const int s = cy * 16 + i;
        outp[(size_t)s * CC + sx] = tile[sx][s];
    }
    float* h1p = g_h1 + ((size_t)n * (HF / 2) + h2) * ((size_t)WF * CC) + c0;
#pragma unroll
    for (int i = 0; i < 8; ++i) {
        const int w = cy * 8 + i;
        h1p[(size_t)w * CC + sx] = fmaxf(tile[sx][w], tile[sx][64 + w]);
    }
}

// ---------------------------------------------------------------------------
// Kernel 2: RoI max pool (R12 structure + bounds prefetch pipeline).
//   grid = (2 channel-halves, 2048 rois), block = 256 threads
//   cg = tid&31 (4 channels, float4), sl = tid>>5 (warp-uniform bin slice)
// h-loop: odd lead row (orig) + aligned row-pairs (H1) + tail row (orig).
// ---------------------------------------------------------------------------
__global__ __launch_bounds__(256, 6)
void roipool_kernel(const float* __restrict__ rois, float* __restrict__ out) {
    __shared__ float sres[128 * 49];

    const int k    = blockIdx.y;
    const int half = blockIdx.x;
    const int tid  = threadIdx.x;
    const int cg   = tid & 31;
    const int sl   = tid >> 5;

    const int b = (int)__ldg(rois + (size_t)k * 5);

    const int coff = half * 32 + cg;
    const float4* base  = (const float4*)g_nhwc + (size_t)b * (HF * WF) * 64 + coff;
    const float4* baseh = (const float4*)g_h1  + (size_t)b * ((HF / 2) * WF) * 64 + coff;

    const float NEG_INF = __int_as_float(0xff800000);

    int bi           = (49 * sl) >> 3;        // 6,6,6,6,6,6,6,7 bins/slice
    const int bi_end = (49 * (sl + 1)) >> 3;

    // prefetch pipeline on the uniform bounds load
    int4 bbn = __ldg(&g_bounds[k * 49 + bi]);

    for (; bi < bi_end; ++bi) {
        const int4 bb = bbn;
        if (bi + 1 < bi_end) bbn = __ldg(&g_bounds[k * 49 + bi + 1]);
        const int hstart = bb.x, hend = bb.y, wstart = bb.z, wend = bb.w;

        float4 m0 = make_float4(NEG_INF, NEG_INF, NEG_INF, NEG_INF);
        float4 m1 = m0;
        const int wc = wend - wstart;

        int h = hstart;
        // odd lead row from orig
        if ((h & 1) && h < hend) {
            const float4* rowp = base + (size_t)(h * WF + wstart) * 64;
            int w = 0;
#pragma unroll 2
            for (; w + 2 <= wc; w += 2) {
                float4 a = __ldg(rowp + (size_t)w * 64);
                float4 c = __ldg(rowp + (size_t)(w + 1) * 64);
                m0 = fmax4(m0, a);
                m1 = fmax4(m1, c);
            }
            if (w < wc) m0 = fmax4(m0, __ldg(rowp + (size_t)w * 64));
            ++h;
        }
        // aligned pairs from H1
        {
            const float4* rowp = baseh + (size_t)((h >> 1) * WF + wstart) * 64;
            for (; h + 2 <= hend; h += 2) {
                int w = 0;
#pragma unroll 2
                for (; w + 2 <= wc; w += 2) {
                    float4 a = __ldg(rowp + (size_t)w * 64);
                    float4 c = __ldg(rowp + (size_t)(w + 1) * 64);
                    m0 = fmax4(m0, a);
                    m1 = fmax4(m1, c);
                }
                if (w < wc) m0 = fmax4(m0, __ldg(rowp + (size_t)w * 64));
                rowp += (size_t)WF * 64;
            }
        }
        // tail row from orig
        if (h < hend) {
            const float4* rowp = base + (size_t)(h * WF + wstart) * 64;
            int w = 0;
#pragma unroll 2
            for (; w + 2 <= wc; w += 2) {
                float4 a = __ldg(rowp + (size_t)w * 64);
                float4 c = __ldg(rowp + (size_t)(w + 1) * 64);
                m0 = fmax4(m0, a);
                m1 = fmax4(m1, c);
            }
            if (w < wc) m0 = fmax4(m0, __ldg(rowp + (size_t)w * 64));
        }

        float4 m = fmax4(m0, m1);
        if (!((hstart < hend) && (wstart < wend)))
            m = make_float4(0.f, 0.f, 0.f, 0.f);

        const int cbase = 4 * cg;
        sres[(cbase + 0) * 49 + bi] = m.x;
        sres[(cbase + 1) * 49 + bi] = m.y;
        sres[(cbase + 2) * 49 + bi] = m.z;
        sres[(cbase + 3) * 49 + bi] = m.w;
    }
    __syncthreads();

    // Contiguous coalesced flush: block owns output span
    // [k*12544 + half*6272, +6272) = 1568 float4.
    float4* outv = (float4*)(out + (size_t)k * (CC * 49) + (size_t)half * (128 * 49));
    const float4* sv = (const float4*)sres;
#pragma unroll
    for (int i = 0; i < 6; ++i) {
        int t = tid + i * 256;
        outv[t] = sv[t];
    }
    if (tid < 1568 - 6 * 256) {
        int t = tid + 6 * 256;
        outv[t] = sv[t];
    }
}

extern "C" void kernel_launch(void* const* d_in, const int* in_sizes, int n_in,
                              void* d_out, int out_size) {
    const float* input = (const float*)d_in[0];   // [4,256,64,64] fp32
    const float* rois  = (const float*)d_in[1];   // [2048,5] fp32
    float* out = (float*)d_out;                   // [2048,256,7,7] fp32

    transpose_build<<<dim3(HF / 2, CC / 32, NB), dim3(32, 8)>>>(input, rois);

    roipool_kernel<<<dim3(2, KK), 256>>>(rois, out);
}

// round 14
// speedup vs baseline: 1.1765x; 1.1765x over previous
#include <cuda_runtime.h>
#include <cstdint>

#define HF 64
#define WF 64
#define CC 256
#define NB 4
#define KK 2048

// NHWC feature map: [N][64][64][C] = 16 MB
__device__ float g_nhwc[NB * HF * WF * CC];
// Row-pair max: H1[n][h2][w][c] = max over rows {2h2, 2h2+1}   (8 MB)
__device__ float g_h1[NB * (HF / 2) * WF * CC];
// Per-(roi,bin) window bounds, packed: (hs, he, ws, we)         (1.6 MB)
__device__ int4 g_bounds[KK * 49];

__device__ __forceinline__ float4 fmax4(float4 a, float4 b) {
    a.x = fmaxf(a.x, b.x);
    a.y = fmaxf(a.y, b.y);
    a.z = fmaxf(a.z, b.z);
    a.w = fmaxf(a.w, b.w);
    return a;
}

// ---------------------------------------------------------------------------
// Kernel 1 (fused prologue, measured ~4 us total overhead in R13):
// NCHW -> NHWC transpose + H1 row-pair max, PLUS the per-(roi,bin) bounds
// table (first 392 of 1024 blocks compute one 256-entry chunk each — hides
// under the transpose's memory latency).
// grid = (HF/2, CC/32, NB) = (32, 8, 4); 256 threads (32 x 8).
// ---------------------------------------------------------------------------
__global__ void transpose_build(const float* __restrict__ in,
                                const float* __restrict__ rois) {
    __shared__ float tile[32][129];   // stride 129: odd -> conflict-free columns
    const int n  = blockIdx.z;
    const int c0 = blockIdx.y * 32;
    const int h2 = blockIdx.x;
    const int s0 = h2 * 128;          // s = h*WF + w; two rows = 128 contiguous s

    const int tid = threadIdx.y * 32 + threadIdx.x;
    const int sx  = threadIdx.x;      // 0..31
    const int cy  = threadIdx.y;      // 0..7

    // ---- bounds-table side job (blocks 0..391 cover 392*256 = 100352) ----
    const int bid = ((blockIdx.z * gridDim.y) + blockIdx.y) * gridDim.x + blockIdx.x;
    if (bid < (KK * 49 + 255) / 256) {
        const int i = bid * 256 + tid;
        if (i < KK * 49) {
            const int k  = i / 49;
            const int bi = i - k * 49;
            const int ph = bi / 7;
            const int pw = bi - ph * 7;

            const float* r = rois + (size_t)k * 5;
            const int rsw = __float2int_rn(r[1] * 0.0625f);  // round-half-even
            const int rsh = __float2int_rn(r[2] * 0.0625f);
            const int rew = __float2int_rn(r[3] * 0.0625f);
            const int reh = __float2int_rn(r[4] * 0.0625f);
            // Reciprocal-multiply division matches the reference's XLA
            // lowering (verified R2: rel_err == 0). Do not change.
            const float RCP7  = 1.0f / 7.0f;
            const float bin_h = (float)max(reh - rsh + 1, 1) * RCP7;
            const float bin_w = (float)max(rew - rsw + 1, 1) * RCP7;

            int hs = min(max((int)floorf((float)ph * bin_h) + rsh, 0), HF);
            int he = min(max((int)ceilf((float)(ph + 1) * bin_h) + rsh, 0), HF);
            int ws = min(max((int)floorf((float)pw * bin_w) + rsw, 0), WF);
            int we = min(max((int)ceilf((float)(pw + 1) * bin_w) + rsw, 0), WF);

            g_bounds[i] = make_int4(hs, he, ws, we);
        }
    }

    // ---- transpose + H1 ----
    const float* inp = in + (size_t)n * CC * (HF * WF);
#pragma unroll
    for (int j = 0; j < 32; j += 8) {
#pragma unroll
        for (int i = 0; i < 128; i += 32) {
            tile[cy + j][i + sx] =
                inp[(size_t)(c0 + cy + j) * (HF * WF) + s0 + i + sx];
        }
    }
    __syncthreads();

    float* outp = g_nhwc + ((size_t)n * (HF * WF) + s0) * CC + c0;
#pragma unroll
    for (int i = 0; i < 16; ++i) {
        const int s = cy * 16 + i;
        outp[(size_t)s * CC + sx] = tile[sx][s];
    }
    float* h1p = g_h1 + ((size_t)n * (HF / 2) + h2) * ((size_t)WF * CC) + c0;
#pragma unroll
    for (int i = 0; i < 8; ++i) {
        const int w = cy * 8 + i;
        h1p[(size_t)w * CC + sx] = fmaxf(tile[sx][w], tile[sx][64 + w]);
    }
}

// ---------------------------------------------------------------------------
// Kernel 2: RoI max pool — byte-exact R12 loop (measured ~87 us; the R13
// bounds-prefetch regressed it and is reverted).
//   grid = (2 channel-halves, 2048 rois), block = 256 threads
//   cg = tid&31 (4 channels, float4), sl = tid>>5 (warp-uniform bin slice)
// h-loop: odd lead row (orig) + aligned row-pairs (H1) + tail row (orig).
// ---------------------------------------------------------------------------
__global__ __launch_bounds__(256, 6)
void roipool_kernel(const float* __restrict__ rois, float* __restrict__ out) {
    __shared__ float sres[128 * 49];

    const int k    = blockIdx.y;
    const int half = blockIdx.x;
    const int tid  = threadIdx.x;
    const int cg   = tid & 31;
    const int sl   = tid >> 5;

    const int b = (int)__ldg(rois + (size_t)k * 5);

    const int coff = half * 32 + cg;
    const float4* base  = (const float4*)g_nhwc + (size_t)b * (HF * WF) * 64 + coff;
    const float4* baseh = (const float4*)g_h1  + (size_t)b * ((HF / 2) * WF) * 64 + coff;

    const float NEG_INF = __int_as_float(0xff800000);

    int bi           = (49 * sl) >> 3;        // 6,6,6,6,6,6,6,7 bins/slice
    const int bi_end = (49 * (sl + 1)) >> 3;

    for (; bi < bi_end; ++bi) {
        // one uniform LDG.128 replaces the per-bin boundary math
        const int4 bb = __ldg(&g_bounds[k * 49 + bi]);
        const int hstart = bb.x, hend = bb.y, wstart = bb.z, wend = bb.w;

        float4 m0 = make_float4(NEG_INF, NEG_INF, NEG_INF, NEG_INF);
        float4 m1 = m0;
        const int wc = wend - wstart;

        int h = hstart;
        // odd lead row from orig
        if ((h & 1) && h < hend) {
            const float4* rowp = base + (size_t)(h * WF + wstart) * 64;
            int w = 0;
#pragma unroll 2
            for (; w + 2 <= wc; w += 2) {
                float4 a = __ldg(rowp + (size_t)w * 64);
                float4 c = __ldg(rowp + (size_t)(w + 1) * 64);
                m0 = fmax4(m0, a);
                m1 = fmax4(m1, c);
            }
            if (w < wc) m0 = fmax4(m0, __ldg(rowp + (size_t)w * 64));
            ++h;
        }
        // aligned pairs from H1
        {
            const float4* rowp = baseh + (size_t)((h >> 1) * WF + wstart) * 64;
            for (; h + 2 <= hend; h += 2) {
                int w = 0;
#pragma unroll 2
                for (; w + 2 <= wc; w += 2) {
                    float4 a = __ldg(rowp + (size_t)w * 64);
                    float4 c = __ldg(rowp + (size_t)(w + 1) * 64);
                    m0 = fmax4(m0, a);
                    m1 = fmax4(m1, c);
                }
                if (w < wc) m0 = fmax4(m0, __ldg(rowp + (size_t)w * 64));
                rowp += (size_t)WF * 64;
            }
        }
        // tail row from orig
        if (h < hend) {
            const float4* rowp = base + (size_t)(h * WF + wstart) * 64;
            int w = 0;
#pragma unroll 2
            for (; w + 2 <= wc; w += 2) {
                float4 a = __ldg(rowp + (size_t)w * 64);
                float4 c = __ldg(rowp + (size_t)(w + 1) * 64);
                m0 = fmax4(m0, a);
                m1 = fmax4(m1, c);
            }
            if (w < wc) m0 = fmax4(m0, __ldg(rowp + (size_t)w * 64));
        }

        float4 m = fmax4(m0, m1);
        if (!((hstart < hend) && (wstart < wend)))
            m = make_float4(0.f, 0.f, 0.f, 0.f);

        const int cbase = 4 * cg;
        sres[(cbase + 0) * 49 + bi] = m.x;
        sres[(cbase + 1) * 49 + bi] = m.y;
        sres[(cbase + 2) * 49 + bi] = m.z;
        sres[(cbase + 3) * 49 + bi] = m.w;
    }
    __syncthreads();

    // Contiguous coalesced flush: block owns output span
    // [k*12544 + half*6272, +6272) = 1568 float4.
    float4* outv = (float4*)(out + (size_t)k * (CC * 49) + (size_t)half * (128 * 49));
    const float4* sv = (const float4*)sres;
#pragma unroll
    for (int i = 0; i < 6; ++i) {
        int t = tid + i * 256;
        outv[t] = sv[t];
    }
    if (tid < 1568 - 6 * 256) {
        int t = tid + 6 * 256;
        outv[t] = sv[t];
    }
}

extern "C" void kernel_launch(void* const* d_in, const int* in_sizes, int n_in,
                              void* d_out, int out_size) {
    const float* input = (const float*)d_in[0];   // [4,256,64,64] fp32
    const float* rois  = (const float*)d_in[1];   // [2048,5] fp32
    float* out = (float*)d_out;                   // [2048,256,7,7] fp32

    transpose_build<<<dim3(HF / 2, CC / 32, NB), dim3(32, 8)>>>(input, rois);

    roipool_kernel<<<dim3(2, KK), 256>>>(rois, out);
}

// round 15
// speedup vs baseline: 1.2105x; 1.0289x over previous
#include <cuda_runtime.h>
#include <cstdint>

#define HF 64
#define WF 64
#define CC 256
#define NB 4
#define KK 2048

// NHWC feature map: [N][64][64][C] = 16 MB
__device__ float g_nhwc[NB * HF * WF * CC];
// Row-pair max: H1[n][h2][w][c] = max rows {2h2, 2h2+1}          (8 MB)
__device__ float g_h1[NB * (HF / 2) * WF * CC];
// Row-quad max: H2[n][h4][w][c] = max rows {4h4 .. 4h4+3}        (4 MB)
__device__ float g_h2[NB * (HF / 4) * WF * CC];
// Per-(roi,bin) window bounds, packed: (hs, he, ws, we)          (1.6 MB)
__device__ int4 g_bounds[KK * 49];

__device__ __forceinline__ float4 fmax4(float4 a, float4 b) {
    a.x = fmaxf(a.x, b.x);
    a.y = fmaxf(a.y, b.y);
    a.z = fmaxf(a.z, b.z);
    a.w = fmaxf(a.w, b.w);
    return a;
}

// ---------------------------------------------------------------------------
// Kernel 1 (fused prologue): NCHW -> NHWC transpose + H1 + H2 in one pass,
// PLUS the per-(roi,bin) bounds table (first 392 of 512 blocks compute one
// 256-entry chunk each — hides under the transpose's memory latency).
// Block = 32 channels x 4 full rows (256 spatial). grid = (16, 8, 4).
// ---------------------------------------------------------------------------
__global__ void transpose_build(const float* __restrict__ in,
                                const float* __restrict__ rois) {
    __shared__ float tile[32][257];   // stride 257 (odd): conflict-free columns
    const int n  = blockIdx.z;
    const int c0 = blockIdx.y * 32;
    const int h4 = blockIdx.x;        // 4-row group
    const int s0 = h4 * 256;          // s = h*WF + w; four rows = 256 contiguous s

    const int tid = threadIdx.y * 32 + threadIdx.x;
    const int sx  = threadIdx.x;      // 0..31
    const int cy  = threadIdx.y;      // 0..7

    // ---- bounds-table side job (blocks 0..391 cover 392*256 = 100352) ----
    const int bid = ((blockIdx.z * gridDim.y) + blockIdx.y) * gridDim.x + blockIdx.x;
    if (bid < (KK * 49 + 255) / 256) {
        const int i = bid * 256 + tid;
        if (i < KK * 49) {
            const int k  = i / 49;
            const int bi = i - k * 49;
            const int ph = bi / 7;
            const int pw = bi - ph * 7;

            const float* r = rois + (size_t)k * 5;
            const int rsw = __float2int_rn(r[1] * 0.0625f);  // round-half-even
            const int rsh = __float2int_rn(r[2] * 0.0625f);
            const int rew = __float2int_rn(r[3] * 0.0625f);
            const int reh = __float2int_rn(r[4] * 0.0625f);
            // Reciprocal-multiply division matches the reference's XLA
            // lowering (verified R2: rel_err == 0). Do not change.
            const float RCP7  = 1.0f / 7.0f;
            const float bin_h = (float)max(reh - rsh + 1, 1) * RCP7;
            const float bin_w = (float)max(rew - rsw + 1, 1) * RCP7;

            int hs = min(max((int)floorf((float)ph * bin_h) + rsh, 0), HF);
            int he = min(max((int)ceilf((float)(ph + 1) * bin_h) + rsh, 0), HF);
            int ws = min(max((int)floorf((float)pw * bin_w) + rsw, 0), WF);
            int we = min(max((int)ceilf((float)(pw + 1) * bin_w) + rsw, 0), WF);

            g_bounds[i] = make_int4(hs, he, ws, we);
        }
    }

    // ---- transpose (coalesced loads) ----
    const float* inp = in + (size_t)n * CC * (HF * WF);
#pragma unroll
    for (int j = 0; j < 32; j += 8) {
#pragma unroll
        for (int i = 0; i < 256; i += 32) {
            tile[cy + j][i + sx] =
                inp[(size_t)(c0 + cy + j) * (HF * WF) + s0 + i + sx];
        }
    }
    __syncthreads();

    // NHWC write: lane = channel (coalesced), tile column reads stride 257
    float* outp = g_nhwc + ((size_t)n * (HF * WF) + s0) * CC + c0;
#pragma unroll
    for (int i = 0; i < 32; ++i) {
        const int s = cy * 32 + i;
        outp[(size_t)s * CC + sx] = tile[sx][s];
    }
    // H1: two output rows (global h2 = 2*h4, 2*h4+1)
    float* h1p = g_h1 + ((size_t)n * (HF / 2) + 2 * h4) * ((size_t)WF * CC) + c0;
#pragma unroll
    for (int i = 0; i < 16; ++i) {
        const int idx = cy * 16 + i;        // 0..127
        const int rr  = idx >> 6;           // 0/1 = which H1 row
        const int w   = idx & 63;
        h1p[((size_t)rr * WF + w) * CC + sx] =
            fmaxf(tile[sx][rr * 128 + w], tile[sx][rr * 128 + 64 + w]);
    }
    // H2: one output row (global h4)
    float* h2p = g_h2 + ((size_t)n * (HF / 4) + h4) * ((size_t)WF * CC) + c0;
#pragma unroll
    for (int i = 0; i < 8; ++i) {
        const int w = cy * 8 + i;           // 0..63
        h2p[(size_t)w * CC + sx] =
            fmaxf(fmaxf(tile[sx][w],       tile[sx][64 + w]),
                  fmaxf(tile[sx][128 + w], tile[sx][192 + w]));
    }
}

// ---------------------------------------------------------------------------
// Kernel 2: RoI max pool (R14 structure + H2 quad rows).
//   grid = (2 channel-halves, 2048 rois), block = 256 threads
//   cg = tid&31 (4 channels, float4), sl = tid>>5 (warp-uniform bin slice)
// h-range: odd fine row -> odd pair -> quads (H2) -> tail pair -> tail fine.
// All decomposition branches are per-bin (warp-uniform); the inner w-pair
// loop is byte-identical to R14's.
// ---------------------------------------------------------------------------
__global__ __launch_bounds__(256, 6)
void roipool_kernel(const float* __restrict__ rois, float* __restrict__ out) {
    __shared__ float sres[128 * 49];

    const int k    = blockIdx.y;
    const int half = blockIdx.x;
    const int tid  = threadIdx.x;
    const int cg   = tid & 31;
    const int sl   = tid >> 5;

    const int b = (int)__ldg(rois + (size_t)k * 5);

    const int coff = half * 32 + cg;
    const float4* base   = (const float4*)g_nhwc + (size_t)b * (HF * WF) * 64 + coff;
    const float4* baseh  = (const float4*)g_h1 + (size_t)b * ((HF / 2) * WF) * 64 + coff;
    const float4* baseh2 = (const float4*)g_h2 + (size_t)b * ((HF / 4) * WF) * 64 + coff;

    const float NEG_INF = __int_as_float(0xff800000);

    int bi           = (49 * sl) >> 3;        // 6,6,6,6,6,6,6,7 bins/slice
    const int bi_end = (49 * (sl + 1)) >> 3;

    for (; bi < bi_end; ++bi) {
        // one uniform LDG.128 replaces the per-bin boundary math
        const int4 bb = __ldg(&g_bounds[k * 49 + bi]);
        const int hstart = bb.x, hend = bb.y, wstart = bb.z, wend = bb.w;

        float4 m0 = make_float4(NEG_INF, NEG_INF, NEG_INF, NEG_INF);
        float4 m1 = m0;
        const int wc = wend - wstart;

        // shared inner scan (identical w-pair loop for every level)
        auto scan = [&](const float4* rowp) {
            int w = 0;
#pragma unroll 2
            for (; w + 2 <= wc; w += 2) {
                float4 a = __ldg(rowp + (size_t)w * 64);
                float4 c = __ldg(rowp + (size_t)(w + 1) * 64);
                m0 = fmax4(m0, a);
                m1 = fmax4(m1, c);
            }
            if (w < wc) m0 = fmax4(m0, __ldg(rowp + (size_t)w * 64));
        };

        int h = hstart;
        // odd fine lead row
        if ((h & 1) && h < hend) {
            scan(base + (size_t)(h * WF + wstart) * 64);
            ++h;
        }
        // odd pair lead (h even, h/2 odd)
        if (((h >> 1) & 1) && h + 2 <= hend) {
            scan(baseh + (size_t)((h >> 1) * WF + wstart) * 64);
            h += 2;
        }
        // quads (h multiple of 4)
        for (; h + 4 <= hend; h += 4) {
            scan(baseh2 + (size_t)((h >> 2) * WF + wstart) * 64);
        }
        // tail pair
        if (h + 2 <= hend) {
            scan(baseh + (size_t)((h >> 1) * WF + wstart) * 64);
            h += 2;
        }
        // tail fine row
        if (h < hend) {
            scan(base + (size_t)(h * WF + wstart) * 64);
        }

        float4 m = fmax4(m0, m1);
        if (!((hstart < hend) && (wstart < wend)))
            m = make_float4(0.f, 0.f, 0.f, 0.f);

        const int cbase = 4 * cg;
        sres[(cbase + 0) * 49 + bi] = m.x;
        sres[(cbase + 1) * 49 + bi] = m.y;
        sres[(cbase + 2) * 49 + bi] = m.z;
        sres[(cbase + 3) * 49 + bi] = m.w;
    }
    __syncthreads();

    // Contiguous coalesced flush: block owns output span
    // [k*12544 + half*6272, +6272) = 1568 float4.
    float4* outv = (float4*)(out + (size_t)k * (CC * 49) + (size_t)half * (128 * 49));
    const float4* sv = (const float4*)sres;
#pragma unroll
    for (int i = 0; i < 6; ++i) {
        int t = tid + i * 256;
        outv[t] = sv[t];
    }
    if (tid < 1568 - 6 * 256) {
        int t = tid + 6 * 256;
        outv[t] = sv[t];
    }
}

extern "C" void kernel_launch(void* const* d_in, const int* in_sizes, int n_in,
                              void* d_out, int out_size) {
    const float* input = (const float*)d_in[0];   // [4,256,64,64] fp32
    const float* rois  = (const float*)d_in[1];   // [2048,5] fp32
    float* out = (float*)d_out;                   // [2048,256,7,7] fp32

    transpose_build<<<dim3(HF / 4, CC / 32, NB), dim3(32, 8)>>>(input, rois);

    roipool_kernel<<<dim3(2, KK), 256>>>(rois, out);
}

// round 16
// speedup vs baseline: 1.2373x; 1.0222x over previous
#include <cuda_runtime.h>
#include <cstdint>

#define HF 64
#define WF 64
#define CC 256
#define NB 4
#define KK 2048

// NHWC feature map: [N][64][64][C] = 16 MB
__device__ float g_nhwc[NB * HF * WF * CC];
// Row-pair max: H1[n][h2][w][c] = max rows {2h2, 2h2+1}          (8 MB)
__device__ float g_h1[NB * (HF / 2) * WF * CC];
// Row-quad max: H2[n][h4][w][c] = max rows {4h4 .. 4h4+3}        (4 MB)
__device__ float g_h2[NB * (HF / 4) * WF * CC];
// Per-(roi,bin) window bounds, packed: (hs, he, ws, we)          (1.6 MB)
__device__ int4 g_bounds[KK * 49];
// Cost-descending roi permutation (LPT scheduling)
__device__ int g_perm[KK];

__device__ __forceinline__ float4 fmax4(float4 a, float4 b) {
    a.x = fmaxf(a.x, b.x);
    a.y = fmaxf(a.y, b.y);
    a.z = fmaxf(a.z, b.z);
    a.w = fmaxf(a.w, b.w);
    return a;
}

// ---------------------------------------------------------------------------
// Kernel 1 (fused prologue): NCHW -> NHWC transpose + H1 + H2,
// PLUS bounds table (blocks 0..391) PLUS LPT roi sort (block 511 only,
// counting sort in smem — hidden under the other blocks' transpose work).
// Block = 32 channels x 4 rows. grid = (16, 8, 4) = 512 blocks, 256 thr.
// ---------------------------------------------------------------------------
__global__ void transpose_build(const float* __restrict__ in,
                                const float* __restrict__ rois) {
    __shared__ float tile[32][257];   // stride 257 (odd): conflict-free columns
    const int n  = blockIdx.z;
    const int c0 = blockIdx.y * 32;
    const int h4 = blockIdx.x;        // 4-row group
    const int s0 = h4 * 256;

    const int tid = threadIdx.y * 32 + threadIdx.x;
    const int sx  = threadIdx.x;      // 0..31
    const int cy  = threadIdx.y;      // 0..7

    const int bid = ((blockIdx.z * gridDim.y) + blockIdx.y) * gridDim.x + blockIdx.x;

    // ---- bounds-table side job (blocks 0..391 cover 392*256 = 100352) ----
    if (bid < (KK * 49 + 255) / 256) {
        const int i = bid * 256 + tid;
        if (i < KK * 49) {
            const int k  = i / 49;
            const int bi = i - k * 49;
            const int ph = bi / 7;
            const int pw = bi - ph * 7;

            const float* r = rois + (size_t)k * 5;
            const int rsw = __float2int_rn(r[1] * 0.0625f);  // round-half-even
            const int rsh = __float2int_rn(r[2] * 0.0625f);
            const int rew = __float2int_rn(r[3] * 0.0625f);
            const int reh = __float2int_rn(r[4] * 0.0625f);
            // Reciprocal-multiply division matches the reference's XLA
            // lowering (verified R2: rel_err == 0). Do not change.
            const float RCP7  = 1.0f / 7.0f;
            const float bin_h = (float)max(reh - rsh + 1, 1) * RCP7;
            const float bin_w = (float)max(rew - rsw + 1, 1) * RCP7;

            int hs = min(max((int)floorf((float)ph * bin_h) + rsh, 0), HF);
            int he = min(max((int)ceilf((float)(ph + 1) * bin_h) + rsh, 0), HF);
            int ws = min(max((int)floorf((float)pw * bin_w) + rsw, 0), WF);
            int we = min(max((int)ceilf((float)(pw + 1) * bin_w) + rsw, 0), WF);

            g_bounds[i] = make_int4(hs, he, ws, we);
        }
    }

    // ---- LPT sort side job (block 511 only): counting sort, descending ----
    if (bid == 511) {
        // reuse the (not yet written) tile as int scratch
        int* hist  = (int*)&tile[0][0];          // [256]
        int* start = ((int*)&tile[0][0]) + 256;  // [256]
        int* bkt   = ((int*)&tile[0][0]) + 512;  // [KK] roi -> bucket
        hist[tid] = 0;
        __syncthreads();
        for (int k = tid; k < KK; k += 256) {
            const float* r = rois + (size_t)k * 5;
            const int rsw = __float2int_rn(r[1] * 0.0625f);
            const int rsh = __float2int_rn(r[2] * 0.0625f);
            const int rew = __float2int_rn(r[3] * 0.0625f);
            const int reh = __float2int_rn(r[4] * 0.0625f);
            const int hr = min(max(reh - rsh + 2, 1), HF);   // ~window height
            const int wr = min(max(rew - rsw + 2, 1), WF);
            const int cost = hr * wr;                        // <= 4096
            const int bb   = min(cost >> 4, 255);
            bkt[k] = bb;
            atomicAdd(&hist[bb], 1);
        }
        __syncthreads();
        // start[b] = number of items in buckets > b  (descending order)
        int acc = 0;
        for (int b2 = 255; b2 > tid; --b2) acc += hist[b2];
        start[tid] = acc;
        __syncthreads();
        for (int k = tid; k < KK; k += 256) {
            const int pos = atomicAdd(&start[bkt[k]], 1);
            g_perm[pos] = k;
        }
        __syncthreads();   // scratch reuse barrier before transpose writes
    }

    // ---- transpose (coalesced loads) ----
    const float* inp = in + (size_t)n * CC * (HF * WF);
#pragma unroll
    for (int j = 0; j < 32; j += 8) {
#pragma unroll
        for (int i = 0; i < 256; i += 32) {
            tile[cy + j][i + sx] =
                inp[(size_t)(c0 + cy + j) * (HF * WF) + s0 + i + sx];
        }
    }
    __syncthreads();

    float* outp = g_nhwc + ((size_t)n * (HF * WF) + s0) * CC + c0;
#pragma unroll
    for (int i = 0; i < 32; ++i) {
        const int s = cy * 32 + i;
        outp[(size_t)s * CC + sx] = tile[sx][s];
    }
    // H1: two output rows (global h2 = 2*h4, 2*h4+1)
    float* h1p = g_h1 + ((size_t)n * (HF / 2) + 2 * h4) * ((size_t)WF * CC) + c0;
#pragma unroll
    for (int i = 0; i < 16; ++i) {
        const int idx = cy * 16 + i;
        const int rr  = idx >> 6;
        const int w   = idx & 63;
        h1p[((size_t)rr * WF + w) * CC + sx] =
            fmaxf(tile[sx][rr * 128 + w], tile[sx][rr * 128 + 64 + w]);
    }
    // H2: one output row (global h4)
    float* h2p = g_h2 + ((size_t)n * (HF / 4) + h4) * ((size_t)WF * CC) + c0;
#pragma unroll
    for (int i = 0; i < 8; ++i) {
        const int w = cy * 8 + i;
        h2p[(size_t)w * CC + sx] =
            fmaxf(fmaxf(tile[sx][w],       tile[sx][64 + w]),
                  fmaxf(tile[sx][128 + w], tile[sx][192 + w]));
    }
}

// ---------------------------------------------------------------------------
// Kernel 2: RoI max pool (R15 structure; roi picked via LPT permutation).
//   grid = (2 channel-halves, 2048 perm slots), block = 256 threads
//   cg = tid&31 (4 channels, float4), sl = tid>>5 (warp-uniform bin slice)
// ---------------------------------------------------------------------------
__global__ __launch_bounds__(256, 6)
void roipool_kernel(const float* __restrict__ rois, float* __restrict__ out) {
    __shared__ float sres[128 * 49];

    const int k    = __ldg(&g_perm[blockIdx.y]);   // LPT: big rois first
    const int half = blockIdx.x;
    const int tid  = threadIdx.x;
    const int cg   = tid & 31;
    const int sl   = tid >> 5;

    const int b = (int)__ldg(rois + (size_t)k * 5);

    const int coff = half * 32 + cg;
    const float4* base   = (const float4*)g_nhwc + (size_t)b * (HF * WF) * 64 + coff;
    const float4* baseh  = (const float4*)g_h1 + (size_t)b * ((HF / 2) * WF) * 64 + coff;
    const float4* baseh2 = (const float4*)g_h2 + (size_t)b * ((HF / 4) * WF) * 64 + coff;

    const float NEG_INF = __int_as_float(0xff800000);

    int bi           = (49 * sl) >> 3;        // 6,6,6,6,6,6,6,7 bins/slice
    const int bi_end = (49 * (sl + 1)) >> 3;

    for (; bi < bi_end; ++bi) {
        const int4 bb = __ldg(&g_bounds[k * 49 + bi]);
        const int hstart = bb.x, hend = bb.y, wstart = bb.z, wend = bb.w;

        float4 m0 = make_float4(NEG_INF, NEG_INF, NEG_INF, NEG_INF);
        float4 m1 = m0;
        const int wc = wend - wstart;

        auto scan = [&](const float4* rowp) {
            int w = 0;
#pragma unroll 2
            for (; w + 2 <= wc; w += 2) {
                float4 a = __ldg(rowp + (size_t)w * 64);
                float4 c = __ldg(rowp + (size_t)(w + 1) * 64);
                m0 = fmax4(m0, a);
                m1 = fmax4(m1, c);
            }
            if (w < wc) m0 = fmax4(m0, __ldg(rowp + (size_t)w * 64));
        };

        int h = hstart;
        if ((h & 1) && h < hend) {                       // odd fine lead row
            scan(base + (size_t)(h * WF + wstart) * 64);
            ++h;
        }
        if (((h >> 1) & 1) && h + 2 <= hend) {           // odd pair lead
            scan(baseh + (size_t)((h >> 1) * WF + wstart) * 64);
            h += 2;
        }
        for (; h + 4 <= hend; h += 4) {                  // quads
            scan(baseh2 + (size_t)((h >> 2) * WF + wstart) * 64);
        }
        if (h + 2 <= hend) {                             // tail pair
            scan(baseh + (size_t)((h >> 1) * WF + wstart) * 64);
            h += 2;
        }
        if (h < hend) {                                  // tail fine row
            scan(base + (size_t)(h * WF + wstart) * 64);
        }

        float4 m = fmax4(m0, m1);
        if (!((hstart < hend) && (wstart < wend)))
            m = make_float4(0.f, 0.f, 0.f, 0.f);

        const int cbase = 4 * cg;
        sres[(cbase + 0) * 49 + bi] = m.x;
        sres[(cbase + 1) * 49 + bi] = m.y;
        sres[(cbase + 2) * 49 + bi] = m.z;
        sres[(cbase + 3) * 49 + bi] = m.w;
    }
    __syncthreads();

    // Contiguous coalesced flush: block owns output span
    // [k*12544 + half*6272, +6272) = 1568 float4.
    float4* outv = (float4*)(out + (size_t)k * (CC * 49) + (size_t)half * (128 * 49));
    const float4* sv = (const float4*)sres;
#pragma unroll
    for (int i = 0; i < 6; ++i) {
        int t = tid + i * 256;
        outv[t] = sv[t];
    }
    if (tid < 1568 - 6 * 256) {
        int t = tid + 6 * 256;
        outv[t] = sv[t];
    }
}

extern "C" void kernel_launch(void* const* d_in, const int* in_sizes, int n_in,
                              void* d_out, int out_size) {
    const float* input = (const float*)d_in[0];   // [4,256,64,64] fp32
    const float* rois  = (const float*)d_in[1];   // [2048,5] fp32
    float* out = (float*)d_out;                   // [2048,256,7,7] fp32

    transpose_build<<<dim3(HF / 4, CC / 32, NB), dim3(32, 8)>>>(input, rois);

    roipool_kernel<<<dim3(2, KK), 256>>>(rois, out);
}

// round 17
// speedup vs baseline: 1.2596x; 1.0180x over previous
#include <cuda_runtime.h>
#include <cstdint>

#define HF 64
#define WF 64
#define CC 256
#define NB 4
#define KK 2048

// NHWC feature map: [N][64][64][C] = 16 MB
__device__ float g_nhwc[NB * HF * WF * CC];
// Row-pair max: H1[n][h2][w][c] = max rows {2h2, 2h2+1}          (8 MB)
__device__ float g_h1[NB * (HF / 2) * WF * CC];
// Row-quad max: H2[n][h4][w][c] = max rows {4h4 .. 4h4+3}        (4 MB)
__device__ float g_h2[NB * (HF / 4) * WF * CC];
// Per-(roi,bin) window bounds, packed: (hs, he, ws, we)          (1.6 MB)
__device__ int4 g_bounds[KK * 49];
// Cost-descending roi permutation (LPT scheduling)
__device__ int g_perm[KK];

__device__ __forceinline__ float4 fmax4(float4 a, float4 b) {
    a.x = fmaxf(a.x, b.x);
    a.y = fmaxf(a.y, b.y);
    a.z = fmaxf(a.z, b.z);
    a.w = fmaxf(a.w, b.w);
    return a;
}

// ---------------------------------------------------------------------------
// Kernel 1 (fused prologue): NCHW -> NHWC transpose + H1 + H2,
// PLUS bounds table (blocks 0..391) PLUS LPT roi sort (block 511, now with a
// parallel scan so it no longer dominates the critical path).
// All global stores are STG.128 (4 channels/thread).
// Block = 32 channels x 4 rows. grid = (16, 8, 4) = 512 blocks, 256 thr.
// ---------------------------------------------------------------------------
__global__ void transpose_build(const float* __restrict__ in,
                                const float* __restrict__ rois) {
    __shared__ float tile[32][257];   // stride 257 (odd): conflict-free columns
    const int n  = blockIdx.z;
    const int c0 = blockIdx.y * 32;
    const int h4 = blockIdx.x;        // 4-row group
    const int s0 = h4 * 256;

    const int tid = threadIdx.y * 32 + threadIdx.x;
    const int sx  = threadIdx.x;      // 0..31
    const int cy  = threadIdx.y;      // 0..7

    const int bid = ((blockIdx.z * gridDim.y) + blockIdx.y) * gridDim.x + blockIdx.x;

    // ---- bounds-table side job (blocks 0..391 cover 392*256 = 100352) ----
    if (bid < (KK * 49 + 255) / 256) {
        const int i = bid * 256 + tid;
        if (i < KK * 49) {
            const int k  = i / 49;
            const int bi = i - k * 49;
            const int ph = bi / 7;
            const int pw = bi - ph * 7;

            const float* r = rois + (size_t)k * 5;
            const int rsw = __float2int_rn(r[1] * 0.0625f);  // round-half-even
            const int rsh = __float2int_rn(r[2] * 0.0625f);
            const int rew = __float2int_rn(r[3] * 0.0625f);
            const int reh = __float2int_rn(r[4] * 0.0625f);
            // Reciprocal-multiply division matches the reference's XLA
            // lowering (verified R2: rel_err == 0). Do not change.
            const float RCP7  = 1.0f / 7.0f;
            const float bin_h = (float)max(reh - rsh + 1, 1) * RCP7;
            const float bin_w = (float)max(rew - rsw + 1, 1) * RCP7;

            int hs = min(max((int)floorf((float)ph * bin_h) + rsh, 0), HF);
            int he = min(max((int)ceilf((float)(ph + 1) * bin_h) + rsh, 0), HF);
            int ws = min(max((int)floorf((float)pw * bin_w) + rsw, 0), WF);
            int we = min(max((int)ceilf((float)(pw + 1) * bin_w) + rsw, 0), WF);

            g_bounds[i] = make_int4(hs, he, ws, we);
        }
    }

    // ---- LPT sort side job (block 511): counting sort w/ parallel scan ----
    if (bid == 511) {
        int* hist = (int*)&tile[0][0];            // [256]
        int* scn  = ((int*)&tile[0][0]) + 256;    // [512] ping-pong scan
        int* strt = ((int*)&tile[0][0]) + 768;    // [256]
        int* bkt  = ((int*)&tile[0][0]) + 1024;   // [KK]
        hist[tid] = 0;
        __syncthreads();
        for (int k = tid; k < KK; k += 256) {
            const float* r = rois + (size_t)k * 5;
            const int rsw = __float2int_rn(r[1] * 0.0625f);
            const int rsh = __float2int_rn(r[2] * 0.0625f);
            const int rew = __float2int_rn(r[3] * 0.0625f);
            const int reh = __float2int_rn(r[4] * 0.0625f);
            const int hr = min(max(reh - rsh + 2, 1), HF);
            const int wr = min(max(rew - rsw + 2, 1), WF);
            const int bb = min((hr * wr) >> 4, 255);
            bkt[k] = bb;
            atomicAdd(&hist[bb], 1);
        }
        __syncthreads();
        // Hillis-Steele inclusive scan over 256 buckets (ping-pong)
        scn[tid] = hist[tid];
        __syncthreads();
        int src = 0;
#pragma unroll
        for (int off = 1; off < 256; off <<= 1) {
            const int v = scn[src * 256 + tid] +
                          ((tid >= off) ? scn[src * 256 + tid - off] : 0);
            scn[(src ^ 1) * 256 + tid] = v;
            src ^= 1;
            __syncthreads();
        }
        const int total = scn[src * 256 + 255];
        strt[tid] = total - scn[src * 256 + tid];   // items in buckets > tid
        __syncthreads();
        for (int k = tid; k < KK; k += 256) {
            const int pos = atomicAdd(&strt[bkt[k]], 1);
            g_perm[pos] = k;
        }
        __syncthreads();   // scratch reuse barrier before transpose fill
    }

    // ---- transpose fill (coalesced scalar loads) ----
    const float* inp = in + (size_t)n * CC * (HF * WF);
#pragma unroll
    for (int j = 0; j < 32; j += 8) {
#pragma unroll
        for (int i = 0; i < 256; i += 32) {
            tile[cy + j][i + sx] =
                inp[(size_t)(c0 + cy + j) * (HF * WF) + s0 + i + sx];
        }
    }
    __syncthreads();

    const int cq = tid & 7;          // channel quad within the 32-channel slab
    const int cc = 4 * cq;

    // NHWC store: 2048 float4; thread -> (s = idx>>3, channel quad)
    float4* outp = (float4*)(g_nhwc + ((size_t)n * (HF * WF) + s0) * CC + c0);
#pragma unroll
    for (int p = 0; p < 8; ++p) {
        const int idx = p * 256 + tid;
        const int s   = idx >> 3;
        float4 v;
        v.x = tile[cc + 0][s];
        v.y = tile[cc + 1][s];
        v.z = tile[cc + 2][s];
        v.w = tile[cc + 3][s];
        outp[(size_t)s * 64 + cq] = v;
    }
    // H1 store: 1024 float4 (two rows of 64 w)
    float4* h1p = (float4*)(g_h1 + ((size_t)n * (HF / 2) + 2 * h4) * ((size_t)WF * CC) + c0);
#pragma unroll
    for (int p = 0; p < 4; ++p) {
        const int idx  = p * 256 + tid;
        const int w128 = idx >> 3;        // 0..127
        const int rr   = w128 >> 6;       // H1 row 0/1
        const int w    = w128 & 63;
        const int sA   = rr * 128 + w;
        const int sB   = sA + 64;
        float4 v;
        v.x = fmaxf(tile[cc + 0][sA], tile[cc + 0][sB]);
        v.y = fmaxf(tile[cc + 1][sA], tile[cc + 1][sB]);
        v.z = fmaxf(tile[cc + 2][sA], tile[cc + 2][sB]);
        v.w = fmaxf(tile[cc + 3][sA], tile[cc + 3][sB]);
        h1p[((size_t)rr * WF + w) * 64 + cq] = v;
    }
    // H2 store: 512 float4 (one row of 64 w)
    float4* h2p = (float4*)(g_h2 + ((size_t)n * (HF / 4) + h4) * ((size_t)WF * CC) + c0);
#pragma unroll
    for (int p = 0; p < 2; ++p) {
        const int idx = p * 256 + tid;
        const int w   = idx >> 3;         // 0..63
        float4 v;
#pragma unroll
        for (int j = 0; j < 4; ++j) {
            float m = fmaxf(fmaxf(tile[cc + j][w],       tile[cc + j][64 + w]),
                            fmaxf(tile[cc + j][128 + w], tile[cc + j][192 + w]));
            ((float*)&v)[j] = m;
        }
        h2p[(size_t)w * 64 + cq] = v;
    }
}

// ---------------------------------------------------------------------------
// Kernel 2: RoI max pool — byte-exact R16 (measured 81.0 us). Frozen.
//   grid = (2 channel-halves, 2048 perm slots), block = 256 threads
//   cg = tid&31 (4 channels, float4), sl = tid>>5 (warp-uniform bin slice)
// ---------------------------------------------------------------------------
__global__ __launch_bounds__(256, 6)
void roipool_kernel(const float* __restrict__ rois, float* __restrict__ out) {
    __shared__ float sres[128 * 49];

    const int k    = __ldg(&g_perm[blockIdx.y]);   // LPT: big rois first
    const int half = blockIdx.x;
    const int tid  = threadIdx.x;
    const int cg   = tid & 31;
    const int sl   = tid >> 5;

    const int b = (int)__ldg(rois + (size_t)k * 5);

    const int coff = half * 32 + cg;
    const float4* base   = (const float4*)g_nhwc + (size_t)b * (HF * WF) * 64 + coff;
    const float4* baseh  = (const float4*)g_h1 + (size_t)b * ((HF / 2) * WF) * 64 + coff;
    const float4* baseh2 = (const float4*)g_h2 + (size_t)b * ((HF / 4) * WF) * 64 + coff;

    const float NEG_INF = __int_as_float(0xff800000);

    int bi           = (49 * sl) >> 3;        // 6,6,6,6,6,6,6,7 bins/slice
    const int bi_end = (49 * (sl + 1)) >> 3;

    for (; bi < bi_end; ++bi) {
        const int4 bb = __ldg(&g_bounds[k * 49 + bi]);
        const int hstart = bb.x, hend = bb.y, wstart = bb.z, wend = bb.w;

        float4 m0 = make_float4(NEG_INF, NEG_INF, NEG_INF, NEG_INF);
        float4 m1 = m0;
        const int wc = wend - wstart;

        auto scan = [&](const float4* rowp) {
            int w = 0;
#pragma unroll 2
            for (; w + 2 <= wc; w += 2) {
                float4 a = __ldg(rowp + (size_t)w * 64);
                float4 c = __ldg(rowp + (size_t)(w + 1) * 64);
                m0 = fmax4(m0, a);
                m1 = fmax4(m1, c);
            }
            if (w < wc) m0 = fmax4(m0, __ldg(rowp + (size_t)w * 64));
        };

        int h = hstart;
        if ((h & 1) && h < hend) {                       // odd fine lead row
            scan(base + (size_t)(h * WF + wstart) * 64);
            ++h;
        }
        if (((h >> 1) & 1) && h + 2 <= hend) {           // odd pair lead
            scan(baseh + (size_t)((h >> 1) * WF + wstart) * 64);
            h += 2;
        }
        for (; h + 4 <= hend; h += 4) {                  // quads
            scan(baseh2 + (size_t)((h >> 2) * WF + wstart) * 64);
        }
        if (h + 2 <= hend) {                             // tail pair
            scan(baseh + (size_t)((h >> 1) * WF + wstart) * 64);
            h += 2;
        }
        if (h < hend) {                                  // tail fine row
            scan(base + (size_t)(h * WF + wstart) * 64);
        }

        float4 m = fmax4(m0, m1);
        if (!((hstart < hend) && (wstart < wend)))
            m = make_float4(0.f, 0.f, 0.f, 0.f);

        const int cbase = 4 * cg;
        sres[(cbase + 0) * 49 + bi] = m.x;
        sres[(cbase + 1) * 49 + bi] = m.y;
        sres[(cbase + 2) * 49 + bi] = m.z;
        sres[(cbase + 3) * 49 + bi] = m.w;
    }
    __syncthreads();

    // Contiguous coalesced flush: block owns output span
    // [k*12544 + half*6272, +6272) = 1568 float4.
    float4* outv = (float4*)(out + (size_t)k * (CC * 49) + (size_t)half * (128 * 49));
    const float4* sv = (const float4*)sres;
#pragma unroll
    for (int i = 0; i < 6; ++i) {
        int t = tid + i * 256;
        outv[t] = sv[t];
    }
    if (tid < 1568 - 6 * 256) {
        int t = tid + 6 * 256;
        outv[t] = sv[t];
    }
}

extern "C" void kernel_launch(void* const* d_in, const int* in_sizes, int n_in,
                              void* d_out, int out_size) {
    const float* input = (const float*)d_in[0];   // [4,256,64,64] fp32
    const float* rois  = (const float*)d_in[1];   // [2048,5] fp32
    float* out = (float*)d_out;                   // [2048,256,7,7] fp32

    transpose_build<<<dim3(HF / 4, CC / 32, NB), dim3(32, 8)>>>(input, rois);

    roipool_kernel<<<dim3(2, KK), 256>>>(rois, out);
}